// round 11
// baseline (speedup 1.0000x reference)
#include <cuda_runtime.h>
#include <cuda_fp16.h>
#include <cstdint>

// Block-causal attention, mma.sync fp16 (fp32 accumulate).
// Round-11: prep grid doubled (occupancy-bound fix); combine fused into the
// main kernel tail via last-split-CTA reduction (threadfence + counter),
// removing the separate combine launch. KSPLIT=4, fp16 partials, cp.async
// double-buffered K/Vt streaming, ex2.f16x2 softmax, ones-fragment l-MMA.

#define SEQ 2048
#define DH  64
#define QT  128
#define ST  64
#define PITCHB 144
#define KS  4

#define SM_Q    0
#define SM_KV0  (SM_Q + 128 * PITCHB)        // 18432
#define SM_KV1  (SM_KV0 + 128 * PITCHB)      // 36864
#define SM_TOTAL (SM_KV1 + 128 * PITCHB)     // 55296
#define KVBUF   (128 * PITCHB)
#define VOFF    (64 * PITCHB)

__device__ __half g_kh[8 * SEQ * DH];        // fp16 K   [n][s][d]
__device__ __half g_vt[8 * DH * SEQ];        // fp16 V^T [n][v][s]
__device__ __half g_scr[KS][8 * SEQ * DH];   // fp16 partials
__device__ float  g_l[KS][8 * SEQ];
__device__ unsigned int g_cnt[8 * 16];       // per-(n,qb) arrival counters (zero-init)

__device__ __forceinline__ uint32_t smem_u32(const void* p) {
    uint32_t a;
    asm("{ .reg .u64 t; cvta.to.shared.u64 t, %1; cvt.u32.u64 %0, t; }"
        : "=r"(a) : "l"(p));
    return a;
}
__device__ __forceinline__ void cp16(uint32_t smem, const __half* g) {
    asm volatile("cp.async.cg.shared.global [%0], [%1], 16;"
                 :: "r"(smem), "l"(__cvta_generic_to_global(g)) : "memory");
}
#define CP_COMMIT() asm volatile("cp.async.commit_group;" ::: "memory")
#define CP_WAIT0()  asm volatile("cp.async.wait_group 0;" ::: "memory")

#define LDSM_X4(r, a) \
    asm volatile("ldmatrix.sync.aligned.m8n8.x4.shared.b16 {%0,%1,%2,%3}, [%4];" \
        : "=r"((r)[0]), "=r"((r)[1]), "=r"((r)[2]), "=r"((r)[3]) : "r"(a))

__device__ __forceinline__ void mma_f16(float* c, const uint32_t* a, const uint32_t* b) {
    asm volatile(
        "mma.sync.aligned.m16n8k16.row.col.f32.f16.f16.f32 "
        "{%0,%1,%2,%3}, {%4,%5,%6,%7}, {%8,%9}, {%0,%1,%2,%3};"
        : "+f"(c[0]), "+f"(c[1]), "+f"(c[2]), "+f"(c[3])
        : "r"(a[0]), "r"(a[1]), "r"(a[2]), "r"(a[3]), "r"(b[0]), "r"(b[1]));
}
__device__ __forceinline__ uint32_t packh(__half a, __half b) {
    __half2 t; t.x = a; t.y = b;
    return *reinterpret_cast<uint32_t*>(&t);
}
__device__ __forceinline__ uint4 cvt8h(const float* x) {
    uint32_t h[4];
#pragma unroll
    for (int m = 0; m < 4; m++)
        h[m] = packh(__float2half_rn(x[2 * m]), __float2half_rn(x[2 * m + 1]));
    return make_uint4(h[0], h[1], h[2], h[3]);
}
__device__ __forceinline__ uint32_t exp2_pair(float lo, float hi) {
    uint32_t t;
    asm("cvt.rn.f16x2.f32 %0, %1, %2;" : "=r"(t) : "f"(hi), "f"(lo));
    asm("ex2.approx.f16x2 %0, %0;" : "+r"(t));
    return t;
}
__device__ __forceinline__ uint32_t pack2h(float a, float b) {
    uint32_t t;
    asm("cvt.rn.f16x2.f32 %0, %1, %2;" : "=r"(t) : "f"(b), "f"(a));
    return t;
}

// ---- pre-pass: K -> fp16 [n][s][d]; V -> fp16 transposed [n][v][s] ----
// grid (64, 8): each CTA handles 32 s-rows. Coalesced in and out; the V
// transpose is staged through swizzled smem.
__global__ __launch_bounds__(256)
void prep_kernel(const float* __restrict__ K, const float* __restrict__ V) {
    __shared__ __align__(16) char vs[32 * PITCHB];
    const int s0 = blockIdx.x * 32, n = blockIdx.y;
    const int tid = threadIdx.x;
    const int r = tid >> 3, d8 = (tid & 7) * 8;     // 32 rows x 8 chunks

    float x[8];
    const float* kp = K + (size_t)(n * SEQ + s0 + r) * DH + d8;
    *(float4*)&x[0] = *(const float4*)kp;
    *(float4*)&x[4] = *(const float4*)(kp + 4);
    *(uint4*)&g_kh[(size_t)(n * SEQ + s0 + r) * DH + d8] = cvt8h(x);

    float y[8];
    const float* vp = V + (size_t)(n * SEQ + s0 + r) * DH + d8;
    *(float4*)&y[0] = *(const float4*)vp;
    *(float4*)&y[4] = *(const float4*)(vp + 4);
    const uint32_t off = r * PITCHB + ((d8 * 2) ^ (((r >> 3) & 7) * 16));
    *(uint4*)(vs + off) = cvt8h(y);
    __syncthreads();

    // transposed write-out: thread (v, s8): v = tid>>2 (0..63), s8 = (tid&3)*8
    const int v = tid >> 2, s8 = (tid & 3) * 8;
    uint32_t wv[4];
#pragma unroll
    for (int k2 = 0; k2 < 4; k2++) {
        const int r0 = s8 + 2 * k2, r1 = r0 + 1;
        const uint16_t h0 = *(const uint16_t*)
            (vs + r0 * PITCHB + ((2 * v) ^ (((r0 >> 3) & 7) * 16)));
        const uint16_t h1 = *(const uint16_t*)
            (vs + r1 * PITCHB + ((2 * v) ^ (((r1 >> 3) & 7) * 16)));
        wv[k2] = (uint32_t)h0 | ((uint32_t)h1 << 16);
    }
    *(uint4*)&g_vt[(size_t)(n * DH + v) * SEQ + s0 + s8] =
        make_uint4(wv[0], wv[1], wv[2], wv[3]);
}

__global__ __launch_bounds__(256, 2)
void attn_part_kernel(const float* __restrict__ Q, const int* __restrict__ prefix,
                      float* __restrict__ O) {
    extern __shared__ char smem[];
    __shared__ int s_last;
    const uint32_t sb = smem_u32(smem);
    const int tid  = threadIdx.x;
    const int lane = tid & 31;
    const int w    = tid >> 5;
    const int tg   = lane & 3;
    const int g    = lane >> 2;
    const int n    = blockIdx.y;
    const int qb   = blockIdx.x;
    const int sp   = blockIdx.z;
    const int q0   = qb * QT;
    const int P    = prefix[n];
    const int m0   = w * 16;

    // ---- Q tile -> smem fp16 ----
#pragma unroll
    for (int gi = 0; gi < 2; gi++) {
        const int gg = tid + 256 * gi;
        const int r = gg >> 2, d8 = (gg & 3) * 16;
        float x[8];
        const float* qp = Q + (size_t)(n * SEQ + q0 + r) * DH + d8;
        *(float4*)&x[0] = *(const float4*)qp;
        *(float4*)&x[4] = *(const float4*)(qp + 4);
        *(uint4*)(smem + SM_Q + r * PITCHB + d8 * 2) = cvt8h(x);
        float y[8];
        *(float4*)&y[0] = *(const float4*)(qp + 8);
        *(float4*)&y[4] = *(const float4*)(qp + 12);
        *(uint4*)(smem + SM_Q + r * PITCHB + d8 * 2 + 16) = cvt8h(y);
    }
    __syncthreads();

    // ---- Q A-fragments ----
    uint32_t qh[4][4];
    {
        const uint32_t abase = sb + SM_Q + (m0 + (lane & 15)) * PITCHB +
                               ((lane >> 4) & 1) * 16;
#pragma unroll
        for (int kk = 0; kk < 4; kk++) LDSM_X4(qh[kk], abase + kk * 32);
    }

    float oacc[8][4], lacc[4];
#pragma unroll
    for (int j = 0; j < 8; j++)
#pragma unroll
        for (int e = 0; e < 4; e++) oacc[j][e] = 0.0f;
#pragma unroll
    for (int e = 0; e < 4; e++) lacc[e] = 0.0f;

    // ---- tile schedule ----
    const int T = (P + ST - 1) / ST;
    const int dA = qb * 2, dB = qb * 2 + 1;
    const int nPref = (T > sp) ? ((T - sp + 3) >> 2) : 0;
    const bool hasA = (dA >= T) && ((dA & (KS - 1)) == sp);
    const bool hasB = (dB >= T) && ((dB & (KS - 1)) == sp);
    const int nIter = nPref + (hasA ? 1 : 0) + (hasB ? 1 : 0);
    auto tile_of = [&](int it) -> int {
        if (it < nPref) return KS * it + sp;
        if (hasA && it == nPref) return dA;
        return dB;
    };

    // per-thread cp.async slots
    const int kr = tid >> 3, kd8 = (tid & 7) * 8;
    const int kr2 = kr + 32;
    const int vv = tid & 63, vs8 = (tid >> 6) * 8;
    const int vs8b = vs8 + 32;

    auto issue_tile = [&](int t, int buf) {
        const int s0t = t * ST;
        const uint32_t kb = sb + SM_KV0 + buf * KVBUF;
        const uint32_t vb = kb + VOFF;
        cp16(kb + kr  * PITCHB + kd8 * 2, &g_kh[(size_t)(n * SEQ + s0t + kr)  * DH + kd8]);
        cp16(kb + kr2 * PITCHB + kd8 * 2, &g_kh[(size_t)(n * SEQ + s0t + kr2) * DH + kd8]);
        cp16(vb + vv * PITCHB + vs8  * 2, &g_vt[(size_t)(n * DH + vv) * SEQ + s0t + vs8]);
        cp16(vb + vv * PITCHB + vs8b * 2, &g_vt[(size_t)(n * DH + vv) * SEQ + s0t + vs8b]);
        CP_COMMIT();
    };

    const uint32_t boff =
        ((((lane >> 4) & 1) * 8 + (lane & 7)) * PITCHB) + ((lane >> 3) & 1) * 16;

    // constant ones B-fragment for the l-MMA
    const uint32_t bone = (g == 0) ? 0x3C003C00u : 0u;
    const uint32_t bo[2] = { bone, bone };

    if (nIter > 0) issue_tile(tile_of(0), 0);

    const float C = 0.18033688011112042f;   // log2(e)/8
    for (int it = 0; it < nIter; ++it) {
        const int s0 = tile_of(it) * ST;
        const int buf = it & 1;

        CP_WAIT0();
        __syncthreads();

        if (it + 1 < nIter) issue_tile(tile_of(it + 1), buf ^ 1);

        const uint32_t bK = sb + SM_KV0 + buf * KVBUF + boff;
        const uint32_t bV = bK + VOFF;

        // ---- GEMM1: sc = Q @ K^T ----
        float sc[8][4];
#pragma unroll
        for (int j = 0; j < 8; j++)
#pragma unroll
            for (int e = 0; e < 4; e++) sc[j][e] = 0.0f;
#pragma unroll
        for (int jp = 0; jp < 4; jp++) {
            const uint32_t ka = bK + jp * (16 * PITCHB);
#pragma unroll
            for (int kk = 0; kk < 4; kk++) {
                uint32_t bh[4];
                LDSM_X4(bh, ka + kk * 32);
                mma_f16(sc[2 * jp],     qh[kk], bh);
                mma_f16(sc[2 * jp + 1], qh[kk], bh + 2);
            }
        }

        // ---- softmax (maskless fast path for interior tiles) ----
        uint32_t pa[8][2];
        if (s0 + ST <= P) {
#pragma unroll
            for (int j = 0; j < 8; j++) {
                pa[j][0] = exp2_pair(sc[j][0] * C, sc[j][1] * C);
                pa[j][1] = exp2_pair(sc[j][2] * C, sc[j][3] * C);
            }
        } else {
            const int row0 = q0 + m0 + g;
            const int row1 = row0 + 8;
#pragma unroll
            for (int j = 0; j < 8; j++) {
                const int cb = s0 + j * 8 + tg * 2;
                const bool ok0 = (cb < P),     okd0 = ok0 || (cb == row0),
                           okd0b = ok0 || (cb == row1);
                const bool ok1 = (cb + 1 < P), okd1 = ok1 || (cb + 1 == row0),
                           okd1b = ok1 || (cb + 1 == row1);
                const float a0 = okd0  ? sc[j][0] * C : -1e30f;
                const float a1 = okd1  ? sc[j][1] * C : -1e30f;
                const float a2 = okd0b ? sc[j][2] * C : -1e30f;
                const float a3 = okd1b ? sc[j][3] * C : -1e30f;
                pa[j][0] = exp2_pair(a0, a1);
                pa[j][1] = exp2_pair(a2, a3);
            }
        }

        // ---- GEMM2: O += P @ V; l += P @ ones ----
#pragma unroll
        for (int kb = 0; kb < 4; kb++) {
            uint32_t af[4] = { pa[2 * kb][0], pa[2 * kb][1],
                               pa[2 * kb + 1][0], pa[2 * kb + 1][1] };
            mma_f16(lacc, af, bo);
#pragma unroll
            for (int jp = 0; jp < 4; jp++) {
                const uint32_t va = bV + jp * (16 * PITCHB) + kb * 32;
                uint32_t vh[4];
                LDSM_X4(vh, va);
                mma_f16(oacc[2 * jp],     af, vh);
                mma_f16(oacc[2 * jp + 1], af, vh + 2);
            }
        }
    }

    // ---- write fp16 partials + fp32 l ----
    const int row0 = q0 + m0 + g;
    const int row1 = row0 + 8;
    if (tg == 0) {
        g_l[sp][n * SEQ + row0] = lacc[0];
        g_l[sp][n * SEQ + row1] = lacc[2];
    }
    __half* scr = g_scr[sp];
#pragma unroll
    for (int j = 0; j < 8; j++) {
        const int col = j * 8 + tg * 2;
        *(uint32_t*)(scr + (size_t)(n * SEQ + row0) * DH + col) =
            pack2h(oacc[j][0], oacc[j][1]);
        *(uint32_t*)(scr + (size_t)(n * SEQ + row1) * DH + col) =
            pack2h(oacc[j][2], oacc[j][3]);
    }

    // ---- last split CTA for (n,qb) combines all partials ----
    __threadfence();
    __syncthreads();
    if (tid == 0) {
        const unsigned int prev = atomicAdd(&g_cnt[n * 16 + qb], 1u);
        s_last = (prev == KS - 1);
    }
    __syncthreads();
    if (!s_last) return;

    // 128 rows x 64 cols: 2048 float4 groups, 8 per thread
    const size_t base4 = ((size_t)(n * SEQ + q0) * DH) >> 2;   // float4 units
#pragma unroll
    for (int h = 0; h < 8; h++) {
        const int idx = h * 256 + tid;              // group in tile
        const int rl = idx >> 4;                    // local row
        const size_t gi4 = base4 + idx;             // global float4 index
        const int lrow = n * SEQ + q0 + rl;
        float l = 0.0f;
        float4 a = make_float4(0.f, 0.f, 0.f, 0.f);
#pragma unroll
        for (int s = 0; s < KS; s++) {
            const uint2 u = ((const uint2*)g_scr[s])[gi4];
            const __half2 p0 = *reinterpret_cast<const __half2*>(&u.x);
            const __half2 p1 = *reinterpret_cast<const __half2*>(&u.y);
            a.x += __low2float(p0);  a.y += __high2float(p0);
            a.z += __low2float(p1);  a.w += __high2float(p1);
            l += g_l[s][lrow];
        }
        const float inv = 1.0f / l;
        ((float4*)O)[gi4] = make_float4(a.x * inv, a.y * inv, a.z * inv, a.w * inv);
    }
    if (tid == 0) g_cnt[n * 16 + qb] = 0;   // reset for next (graph-replayed) launch
}

extern "C" void kernel_launch(void* const* d_in, const int* in_sizes, int n_in,
                              void* d_out, int out_size) {
    const float* Q      = (const float*)d_in[0];
    const float* K      = (const float*)d_in[1];
    const float* V      = (const float*)d_in[2];
    const int*   prefix = (const int*)d_in[3];
    float*       O      = (float*)d_out;

    prep_kernel<<<dim3(64, 8), 256>>>(K, V);
    cudaFuncSetAttribute(attn_part_kernel,
                         cudaFuncAttributeMaxDynamicSharedMemorySize, SM_TOTAL);
    attn_part_kernel<<<dim3(16, 8, KS), 256, SM_TOTAL>>>(Q, prefix, O);
}

// round 12
// speedup vs baseline: 1.1242x; 1.1242x over previous
#include <cuda_runtime.h>
#include <cuda_fp16.h>
#include <cstdint>

// Block-causal attention, mma.sync fp16 (fp32 accumulate).
// Round-12: round-10 structure (separate combine kernel — fused-combine
// regressed) + round-11's occupancy-fixed prep (grid 64x8, 32-row CTAs).
// KSPLIT=4, fp16 partials, cp.async double-buffered K/Vt streaming,
// ex2.f16x2 softmax, constant ones-fragment l-MMA.

#define SEQ 2048
#define DH  64
#define QT  128
#define ST  64
#define PITCHB 144
#define KS  4

#define SM_Q    0
#define SM_KV0  (SM_Q + 128 * PITCHB)        // 18432
#define SM_KV1  (SM_KV0 + 128 * PITCHB)      // 36864
#define SM_TOTAL (SM_KV1 + 128 * PITCHB)     // 55296
#define KVBUF   (128 * PITCHB)
#define VOFF    (64 * PITCHB)

__device__ __half g_kh[8 * SEQ * DH];        // fp16 K   [n][s][d]
__device__ __half g_vt[8 * DH * SEQ];        // fp16 V^T [n][v][s]
__device__ __half g_scr[KS][8 * SEQ * DH];   // fp16 partials
__device__ float  g_l[KS][8 * SEQ];

__device__ __forceinline__ uint32_t smem_u32(const void* p) {
    uint32_t a;
    asm("{ .reg .u64 t; cvta.to.shared.u64 t, %1; cvt.u32.u64 %0, t; }"
        : "=r"(a) : "l"(p));
    return a;
}
__device__ __forceinline__ void cp16(uint32_t smem, const __half* g) {
    asm volatile("cp.async.cg.shared.global [%0], [%1], 16;"
                 :: "r"(smem), "l"(__cvta_generic_to_global(g)) : "memory");
}
#define CP_COMMIT() asm volatile("cp.async.commit_group;" ::: "memory")
#define CP_WAIT0()  asm volatile("cp.async.wait_group 0;" ::: "memory")

#define LDSM_X4(r, a) \
    asm volatile("ldmatrix.sync.aligned.m8n8.x4.shared.b16 {%0,%1,%2,%3}, [%4];" \
        : "=r"((r)[0]), "=r"((r)[1]), "=r"((r)[2]), "=r"((r)[3]) : "r"(a))

__device__ __forceinline__ void mma_f16(float* c, const uint32_t* a, const uint32_t* b) {
    asm volatile(
        "mma.sync.aligned.m16n8k16.row.col.f32.f16.f16.f32 "
        "{%0,%1,%2,%3}, {%4,%5,%6,%7}, {%8,%9}, {%0,%1,%2,%3};"
        : "+f"(c[0]), "+f"(c[1]), "+f"(c[2]), "+f"(c[3])
        : "r"(a[0]), "r"(a[1]), "r"(a[2]), "r"(a[3]), "r"(b[0]), "r"(b[1]));
}
__device__ __forceinline__ uint32_t packh(__half a, __half b) {
    __half2 t; t.x = a; t.y = b;
    return *reinterpret_cast<uint32_t*>(&t);
}
__device__ __forceinline__ uint4 cvt8h(const float* x) {
    uint32_t h[4];
#pragma unroll
    for (int m = 0; m < 4; m++)
        h[m] = packh(__float2half_rn(x[2 * m]), __float2half_rn(x[2 * m + 1]));
    return make_uint4(h[0], h[1], h[2], h[3]);
}
__device__ __forceinline__ uint32_t exp2_pair(float lo, float hi) {
    uint32_t t;
    asm("cvt.rn.f16x2.f32 %0, %1, %2;" : "=r"(t) : "f"(hi), "f"(lo));
    asm("ex2.approx.f16x2 %0, %0;" : "+r"(t));
    return t;
}
__device__ __forceinline__ uint32_t pack2h(float a, float b) {
    uint32_t t;
    asm("cvt.rn.f16x2.f32 %0, %1, %2;" : "=r"(t) : "f"(b), "f"(a));
    return t;
}

// ---- pre-pass: K -> fp16 [n][s][d]; V -> fp16 transposed [n][v][s] ----
// grid (64, 8): each CTA handles 32 s-rows. Coalesced in and out; the V
// transpose is staged through swizzled smem.
__global__ __launch_bounds__(256)
void prep_kernel(const float* __restrict__ K, const float* __restrict__ V) {
    __shared__ __align__(16) char vs[32 * PITCHB];
    const int s0 = blockIdx.x * 32, n = blockIdx.y;
    const int tid = threadIdx.x;
    const int r = tid >> 3, d8 = (tid & 7) * 8;     // 32 rows x 8 chunks

    float x[8];
    const float* kp = K + (size_t)(n * SEQ + s0 + r) * DH + d8;
    *(float4*)&x[0] = *(const float4*)kp;
    *(float4*)&x[4] = *(const float4*)(kp + 4);
    *(uint4*)&g_kh[(size_t)(n * SEQ + s0 + r) * DH + d8] = cvt8h(x);

    float y[8];
    const float* vp = V + (size_t)(n * SEQ + s0 + r) * DH + d8;
    *(float4*)&y[0] = *(const float4*)vp;
    *(float4*)&y[4] = *(const float4*)(vp + 4);
    const uint32_t off = r * PITCHB + ((d8 * 2) ^ (((r >> 3) & 7) * 16));
    *(uint4*)(vs + off) = cvt8h(y);
    __syncthreads();

    // transposed write-out: thread (v, s8): v = tid>>2 (0..63), s8 = (tid&3)*8
    const int v = tid >> 2, s8 = (tid & 3) * 8;
    uint32_t wv[4];
#pragma unroll
    for (int k2 = 0; k2 < 4; k2++) {
        const int r0 = s8 + 2 * k2, r1 = r0 + 1;
        const uint16_t h0 = *(const uint16_t*)
            (vs + r0 * PITCHB + ((2 * v) ^ (((r0 >> 3) & 7) * 16)));
        const uint16_t h1 = *(const uint16_t*)
            (vs + r1 * PITCHB + ((2 * v) ^ (((r1 >> 3) & 7) * 16)));
        wv[k2] = (uint32_t)h0 | ((uint32_t)h1 << 16);
    }
    *(uint4*)&g_vt[(size_t)(n * DH + v) * SEQ + s0 + s8] =
        make_uint4(wv[0], wv[1], wv[2], wv[3]);
}

__global__ __launch_bounds__(256, 2)
void attn_part_kernel(const float* __restrict__ Q, const int* __restrict__ prefix) {
    extern __shared__ char smem[];
    const uint32_t sb = smem_u32(smem);
    const int tid  = threadIdx.x;
    const int lane = tid & 31;
    const int w    = tid >> 5;
    const int tg   = lane & 3;
    const int g    = lane >> 2;
    const int n    = blockIdx.y;
    const int qb   = blockIdx.x;
    const int sp   = blockIdx.z;
    const int q0   = qb * QT;
    const int P    = prefix[n];
    const int m0   = w * 16;

    // ---- Q tile -> smem fp16 ----
#pragma unroll
    for (int gi = 0; gi < 2; gi++) {
        const int gg = tid + 256 * gi;
        const int r = gg >> 2, d8 = (gg & 3) * 16;
        float x[8];
        const float* qp = Q + (size_t)(n * SEQ + q0 + r) * DH + d8;
        *(float4*)&x[0] = *(const float4*)qp;
        *(float4*)&x[4] = *(const float4*)(qp + 4);
        *(uint4*)(smem + SM_Q + r * PITCHB + d8 * 2) = cvt8h(x);
        float y[8];
        *(float4*)&y[0] = *(const float4*)(qp + 8);
        *(float4*)&y[4] = *(const float4*)(qp + 12);
        *(uint4*)(smem + SM_Q + r * PITCHB + d8 * 2 + 16) = cvt8h(y);
    }
    __syncthreads();

    // ---- Q A-fragments ----
    uint32_t qh[4][4];
    {
        const uint32_t abase = sb + SM_Q + (m0 + (lane & 15)) * PITCHB +
                               ((lane >> 4) & 1) * 16;
#pragma unroll
        for (int kk = 0; kk < 4; kk++) LDSM_X4(qh[kk], abase + kk * 32);
    }

    float oacc[8][4], lacc[4];
#pragma unroll
    for (int j = 0; j < 8; j++)
#pragma unroll
        for (int e = 0; e < 4; e++) oacc[j][e] = 0.0f;
#pragma unroll
    for (int e = 0; e < 4; e++) lacc[e] = 0.0f;

    // ---- tile schedule ----
    const int T = (P + ST - 1) / ST;
    const int dA = qb * 2, dB = qb * 2 + 1;
    const int nPref = (T > sp) ? ((T - sp + 3) >> 2) : 0;
    const bool hasA = (dA >= T) && ((dA & (KS - 1)) == sp);
    const bool hasB = (dB >= T) && ((dB & (KS - 1)) == sp);
    const int nIter = nPref + (hasA ? 1 : 0) + (hasB ? 1 : 0);
    auto tile_of = [&](int it) -> int {
        if (it < nPref) return KS * it + sp;
        if (hasA && it == nPref) return dA;
        return dB;
    };

    // per-thread cp.async slots
    const int kr = tid >> 3, kd8 = (tid & 7) * 8;
    const int kr2 = kr + 32;
    const int vv = tid & 63, vs8 = (tid >> 6) * 8;
    const int vs8b = vs8 + 32;

    auto issue_tile = [&](int t, int buf) {
        const int s0t = t * ST;
        const uint32_t kb = sb + SM_KV0 + buf * KVBUF;
        const uint32_t vb = kb + VOFF;
        cp16(kb + kr  * PITCHB + kd8 * 2, &g_kh[(size_t)(n * SEQ + s0t + kr)  * DH + kd8]);
        cp16(kb + kr2 * PITCHB + kd8 * 2, &g_kh[(size_t)(n * SEQ + s0t + kr2) * DH + kd8]);
        cp16(vb + vv * PITCHB + vs8  * 2, &g_vt[(size_t)(n * DH + vv) * SEQ + s0t + vs8]);
        cp16(vb + vv * PITCHB + vs8b * 2, &g_vt[(size_t)(n * DH + vv) * SEQ + s0t + vs8b]);
        CP_COMMIT();
    };

    const uint32_t boff =
        ((((lane >> 4) & 1) * 8 + (lane & 7)) * PITCHB) + ((lane >> 3) & 1) * 16;

    // constant ones B-fragment for the l-MMA (B[k][0]=1, cols 1..7 = 0)
    const uint32_t bone = (g == 0) ? 0x3C003C00u : 0u;
    const uint32_t bo[2] = { bone, bone };

    if (nIter > 0) issue_tile(tile_of(0), 0);

    const float C = 0.18033688011112042f;   // log2(e)/8
    for (int it = 0; it < nIter; ++it) {
        const int s0 = tile_of(it) * ST;
        const int buf = it & 1;

        CP_WAIT0();
        __syncthreads();  // tile `it` landed; all warps done with buf^1 compute

        if (it + 1 < nIter) issue_tile(tile_of(it + 1), buf ^ 1);

        const uint32_t bK = sb + SM_KV0 + buf * KVBUF + boff;
        const uint32_t bV = bK + VOFF;

        // ---- GEMM1: sc = Q @ K^T ----
        float sc[8][4];
#pragma unroll
        for (int j = 0; j < 8; j++)
#pragma unroll
            for (int e = 0; e < 4; e++) sc[j][e] = 0.0f;
#pragma unroll
        for (int jp = 0; jp < 4; jp++) {
            const uint32_t ka = bK + jp * (16 * PITCHB);
#pragma unroll
            for (int kk = 0; kk < 4; kk++) {
                uint32_t bh[4];
                LDSM_X4(bh, ka + kk * 32);
                mma_f16(sc[2 * jp],     qh[kk], bh);
                mma_f16(sc[2 * jp + 1], qh[kk], bh + 2);
            }
        }

        // ---- softmax (maskless fast path for interior tiles) ----
        uint32_t pa[8][2];
        if (s0 + ST <= P) {
#pragma unroll
            for (int j = 0; j < 8; j++) {
                pa[j][0] = exp2_pair(sc[j][0] * C, sc[j][1] * C);
                pa[j][1] = exp2_pair(sc[j][2] * C, sc[j][3] * C);
            }
        } else {
            const int row0 = q0 + m0 + g;
            const int row1 = row0 + 8;
#pragma unroll
            for (int j = 0; j < 8; j++) {
                const int cb = s0 + j * 8 + tg * 2;
                const bool ok0 = (cb < P),     okd0 = ok0 || (cb == row0),
                           okd0b = ok0 || (cb == row1);
                const bool ok1 = (cb + 1 < P), okd1 = ok1 || (cb + 1 == row0),
                           okd1b = ok1 || (cb + 1 == row1);
                const float a0 = okd0  ? sc[j][0] * C : -1e30f;
                const float a1 = okd1  ? sc[j][1] * C : -1e30f;
                const float a2 = okd0b ? sc[j][2] * C : -1e30f;
                const float a3 = okd1b ? sc[j][3] * C : -1e30f;
                pa[j][0] = exp2_pair(a0, a1);
                pa[j][1] = exp2_pair(a2, a3);
            }
        }

        // ---- GEMM2: O += P @ V; l += P @ ones (constant fragment) ----
#pragma unroll
        for (int kb = 0; kb < 4; kb++) {
            uint32_t af[4] = { pa[2 * kb][0], pa[2 * kb][1],
                               pa[2 * kb + 1][0], pa[2 * kb + 1][1] };
            mma_f16(lacc, af, bo);
#pragma unroll
            for (int jp = 0; jp < 4; jp++) {
                const uint32_t va = bV + jp * (16 * PITCHB) + kb * 32;
                uint32_t vh[4];
                LDSM_X4(vh, va);
                mma_f16(oacc[2 * jp],     af, vh);
                mma_f16(oacc[2 * jp + 1], af, vh + 2);
            }
        }
    }

    // ---- write fp16 partials + fp32 l ----
    const int row0 = q0 + m0 + g;
    const int row1 = row0 + 8;
    if (tg == 0) {
        g_l[sp][n * SEQ + row0] = lacc[0];
        g_l[sp][n * SEQ + row1] = lacc[2];
    }
    __half* scr = g_scr[sp];
#pragma unroll
    for (int j = 0; j < 8; j++) {
        const int col = j * 8 + tg * 2;
        *(uint32_t*)(scr + (size_t)(n * SEQ + row0) * DH + col) =
            pack2h(oacc[j][0], oacc[j][1]);
        *(uint32_t*)(scr + (size_t)(n * SEQ + row1) * DH + col) =
            pack2h(oacc[j][2], oacc[j][3]);
    }
}

__global__ __launch_bounds__(256, 8)
void combine_kernel(float* __restrict__ O) {
    const int i = blockIdx.x * 256 + threadIdx.x;   // float4 index, 262144 total
    const int row = i >> 4;
    float l = 0.0f;
    float4 a = make_float4(0.f, 0.f, 0.f, 0.f);
#pragma unroll
    for (int s = 0; s < KS; s++) {
        const uint2 u = ((const uint2*)g_scr[s])[i];
        const __half2 p0 = *reinterpret_cast<const __half2*>(&u.x);
        const __half2 p1 = *reinterpret_cast<const __half2*>(&u.y);
        a.x += __low2float(p0);  a.y += __high2float(p0);
        a.z += __low2float(p1);  a.w += __high2float(p1);
        l += g_l[s][row];
    }
    const float inv = 1.0f / l;
    ((float4*)O)[i] = make_float4(a.x * inv, a.y * inv, a.z * inv, a.w * inv);
}

extern "C" void kernel_launch(void* const* d_in, const int* in_sizes, int n_in,
                              void* d_out, int out_size) {
    const float* Q      = (const float*)d_in[0];
    const float* K      = (const float*)d_in[1];
    const float* V      = (const float*)d_in[2];
    const int*   prefix = (const int*)d_in[3];
    float*       O      = (float*)d_out;

    prep_kernel<<<dim3(64, 8), 256>>>(K, V);
    cudaFuncSetAttribute(attn_part_kernel,
                         cudaFuncAttributeMaxDynamicSharedMemorySize, SM_TOTAL);
    attn_part_kernel<<<dim3(16, 8, KS), 256, SM_TOTAL>>>(Q, prefix);
    combine_kernel<<<(8 * SEQ * DH / 4) / 256, 256>>>(O);
}